// round 14
// baseline (speedup 1.0000x reference)
#include <cuda_runtime.h>
#include <cuda_bf16.h>
#include <stdint.h>

// Scatter-mean via counting-sort + gather (no atomics in the hot loop).
// Pipeline (5 launches): rank (inline dtype detect + hist + rank-within-node,
// only atomic pass) -> scan_partial -> scan_final (inline tops) -> place
// (atomic-free, 4-wide) -> gather (2-deep pipeline). All read-once/write-once
// traffic uses L1::no_allocate so L1 stays free for hot tables (g_start) and
// the L1tex wavefront queue isn't burned on useless allocations.
// Fallback to a direct-atomic path for shapes exceeding static scratch.

#define MAX_NODES (1 << 20)
#define PERM_CAP  (1 << 21)
#define SCAN_TILE 1024
#define SCAN_THREADS 512
#define MAX_SCAN_BLOCKS ((MAX_NODES + SCAN_TILE - 1) / SCAN_TILE)

__device__ int g_count[MAX_NODES];       // zero at entry of every execution
__device__ int g_start[MAX_NODES];
__device__ int g_rank[PERM_CAP];
__device__ int g_perm[PERM_CAP];
__device__ int g_bsum[MAX_SCAN_BLOCKS];
__device__ float g_fcounts[MAX_NODES];   // fallback path only

// ---- streaming (no L1 allocation) memory helpers ----
__device__ __forceinline__ float4 ldg_stream_v4f(const float4* p) {
    float4 v;
    asm volatile("ld.global.nc.L1::no_allocate.v4.f32 {%0, %1, %2, %3}, [%4];"
                 : "=f"(v.x), "=f"(v.y), "=f"(v.z), "=f"(v.w) : "l"(p));
    return v;
}
__device__ __forceinline__ int4 ldg_stream_v4i(const int4* p) {
    int4 v;
    asm volatile("ld.global.nc.L1::no_allocate.v4.s32 {%0, %1, %2, %3}, [%4];"
                 : "=r"(v.x), "=r"(v.y), "=r"(v.z), "=r"(v.w) : "l"(p));
    return v;
}
__device__ __forceinline__ longlong2 ldg_stream_v2l(const longlong2* p) {
    longlong2 v;
    asm volatile("ld.global.nc.L1::no_allocate.v2.s64 {%0, %1}, [%2];"
                 : "=l"(v.x), "=l"(v.y) : "l"(p));
    return v;
}
__device__ __forceinline__ void stg_stream_b32(int* p, int v) {
    asm volatile("st.global.L1::no_allocate.b32 [%0], %1;" :: "l"(p), "r"(v) : "memory");
}
__device__ __forceinline__ void stg_stream_v4i(int4* p, int4 v) {
    asm volatile("st.global.L1::no_allocate.v4.b32 [%0], {%1, %2, %3, %4};"
                 :: "l"(p), "r"(v.x), "r"(v.y), "r"(v.z), "r"(v.w) : "memory");
}
__device__ __forceinline__ void stg_stream_v4f(float4* p, float4 v) {
    asm volatile("st.global.L1::no_allocate.v4.f32 [%0], {%1, %2, %3, %4};"
                 :: "l"(p), "f"(v.x), "f"(v.y), "f"(v.z), "f"(v.w) : "memory");
}

// Per-block inline dtype detection: examine 256 odd-position 32-bit words from
// this block's own region. int64 ids < 2^32 have all-zero high words; int32
// random ids make some odd word nonzero with overwhelming probability. The
// degenerate all-zero case decodes identically either way.
__device__ __forceinline__ bool detect_is64_block(const unsigned int* words, int M) {
    int t = threadIdx.x & 255;
    int span = M >> 1;                 // number of (even,odd) pairs within M words
    unsigned int w = 0u;
    if (span > 0) {
        int wbase = (int)blockIdx.x * 256;
        if (span > 256) wbase %= (span - 255); else wbase = 0;
        int p = wbase + t;
        if (p < span) w = words[2 * p + 1];
    }
    return __syncthreads_or((int)w) == 0;   // all high words zero -> int64
}

__device__ __forceinline__ int load_id(const void* ids, int i, bool is64) {
    return is64 ? (int)((const long long*)ids)[i] : ((const int*)ids)[i];
}

// Histogram + rank-within-node: the only returning-atomic pass.
// 4 independent atomic chains in flight per thread-iteration.
__global__ void rank_kernel(const void* __restrict__ ids, int M) {
    bool is64 = detect_is64_block((const unsigned int*)ids, M);
    int t = blockIdx.x * blockDim.x + threadIdx.x;
    int stride = gridDim.x * blockDim.x;
    int M4 = M >> 2;
    if (is64) {
        const longlong2* p = (const longlong2*)ids;
        for (int i = t; i < M4; i += stride) {
            longlong2 a = ldg_stream_v2l(&p[2 * i]);
            longlong2 b = ldg_stream_v2l(&p[2 * i + 1]);
            int r0 = atomicAdd(&g_count[(int)a.x], 1);
            int r1 = atomicAdd(&g_count[(int)a.y], 1);
            int r2 = atomicAdd(&g_count[(int)b.x], 1);
            int r3 = atomicAdd(&g_count[(int)b.y], 1);
            stg_stream_v4i(&((int4*)g_rank)[i], make_int4(r0, r1, r2, r3));
        }
    } else {
        const int4* p = (const int4*)ids;
        for (int i = t; i < M4; i += stride) {
            int4 a = ldg_stream_v4i(&p[i]);
            int r0 = atomicAdd(&g_count[a.x], 1);
            int r1 = atomicAdd(&g_count[a.y], 1);
            int r2 = atomicAdd(&g_count[a.z], 1);
            int r3 = atomicAdd(&g_count[a.w], 1);
            stg_stream_v4i(&((int4*)g_rank)[i], make_int4(r0, r1, r2, r3));
        }
    }
    for (int i = M4 * 4 + t; i < M; i += stride)
        g_rank[i] = atomicAdd(&g_count[load_id(ids, i, is64)], 1);
}

// ----- 2-stage scan: partial sums -> final rescan with inline tops scan -----
__global__ void scan_partial(int N) {
    __shared__ int wsum[SCAN_THREADS / 32];
    int b = blockIdx.x, tid = threadIdx.x;
    int lane = tid & 31, warp = tid >> 5;
    int base = b * SCAN_TILE + tid * 2;
    int s = 0;
    #pragma unroll
    for (int k = 0; k < 2; k++) {
        int i = base + k;
        if (i < N) s += g_count[i];
    }
    #pragma unroll
    for (int o = 16; o > 0; o >>= 1) s += __shfl_down_sync(0xffffffffu, s, o);
    if (lane == 0) wsum[warp] = s;
    __syncthreads();
    if (warp == 0) {
        int w = (lane < SCAN_THREADS / 32) ? wsum[lane] : 0;
        #pragma unroll
        for (int o = 16; o > 0; o >>= 1) w += __shfl_down_sync(0xffffffffu, w, o);
        if (lane == 0) g_bsum[b] = w;
    }
}

__global__ void scan_final(int N, int nb) {
    __shared__ int wsum[32];
    __shared__ int sboff[1024];
    int b = blockIdx.x, tid = threadIdx.x;
    int lane = tid & 31, warp = tid >> 5;

    // Inline exclusive scan of the nb block sums (nb <= SCAN_THREADS).
    {
        int s = (tid < nb) ? g_bsum[tid] : 0;
        int x = s;
        #pragma unroll
        for (int o = 1; o < 32; o <<= 1) {
            int y = __shfl_up_sync(0xffffffffu, x, o);
            if (lane >= o) x += y;
        }
        if (lane == 31) wsum[warp] = x;
        __syncthreads();
        if (warp == 0) {
            int w = (lane < SCAN_THREADS / 32) ? wsum[lane] : 0;
            #pragma unroll
            for (int o = 1; o < 32; o <<= 1) {
                int y = __shfl_up_sync(0xffffffffu, w, o);
                if (lane >= o) w += y;
            }
            wsum[lane] = w;
        }
        __syncthreads();
        if (tid < nb) sboff[tid] = x - s + (warp > 0 ? wsum[warp - 1] : 0);
        __syncthreads();
    }
    int boff = sboff[b];
    __syncthreads();   // wsum reuse below

    int base = b * SCAN_TILE + tid * 2;
    int v[2]; int s = 0;
    #pragma unroll
    for (int k = 0; k < 2; k++) {
        int i = base + k;
        v[k] = (i < N) ? g_count[i] : 0;
        s += v[k];
    }
    int x = s;
    #pragma unroll
    for (int o = 1; o < 32; o <<= 1) {
        int y = __shfl_up_sync(0xffffffffu, x, o);
        if (lane >= o) x += y;
    }
    if (lane == 31) wsum[warp] = x;
    __syncthreads();
    if (warp == 0) {
        int w = (lane < SCAN_THREADS / 32) ? wsum[lane] : 0;
        #pragma unroll
        for (int o = 1; o < 32; o <<= 1) {
            int y = __shfl_up_sync(0xffffffffu, w, o);
            if (lane >= o) w += y;
        }
        wsum[lane] = w;
    }
    __syncthreads();
    int run = x - s + (warp > 0 ? wsum[warp - 1] : 0) + boff;
    #pragma unroll
    for (int k = 0; k < 2; k++) {
        int i = base + k;
        if (i < N) {
            g_start[i] = run;
            run += v[k];
        }
    }
}

// Atomic-free permutation: perm[start[id] + rank[i]] = i. 4-wide.
// ids/rank loads and perm stores bypass L1; the hot g_start table (200 KB)
// stays default-cached and can live in the L1 carveout.
__global__ void place_kernel(const void* __restrict__ ids, int M) {
    bool is64 = detect_is64_block((const unsigned int*)ids, M);
    int t = blockIdx.x * blockDim.x + threadIdx.x;
    int stride = gridDim.x * blockDim.x;
    int M4 = M >> 2;
    if (is64) {
        const longlong2* p = (const longlong2*)ids;
        for (int i = t; i < M4; i += stride) {
            longlong2 a = ldg_stream_v2l(&p[2 * i]);
            longlong2 b = ldg_stream_v2l(&p[2 * i + 1]);
            int4 r = ldg_stream_v4i(&((const int4*)g_rank)[i]);
            int base = 4 * i;
            stg_stream_b32(&g_perm[g_start[(int)a.x] + r.x], base);
            stg_stream_b32(&g_perm[g_start[(int)a.y] + r.y], base + 1);
            stg_stream_b32(&g_perm[g_start[(int)b.x] + r.z], base + 2);
            stg_stream_b32(&g_perm[g_start[(int)b.y] + r.w], base + 3);
        }
    } else {
        const int4* p = (const int4*)ids;
        for (int i = t; i < M4; i += stride) {
            int4 a = ldg_stream_v4i(&p[i]);
            int4 r = ldg_stream_v4i(&((const int4*)g_rank)[i]);
            int base = 4 * i;
            stg_stream_b32(&g_perm[g_start[a.x] + r.x], base);
            stg_stream_b32(&g_perm[g_start[a.y] + r.y], base + 1);
            stg_stream_b32(&g_perm[g_start[a.z] + r.z], base + 2);
            stg_stream_b32(&g_perm[g_start[a.w] + r.w], base + 3);
        }
    }
    for (int i = M4 * 4 + t; i < M; i += stride) {
        int id = load_id(ids, i, is64);
        g_perm[g_start[id] + g_rank[i]] = i;
    }
}

// One warp per node; D == 128 (32 float4 per row, 1 per lane), 2-deep pipeline.
// Row loads and output stores bypass L1. Also writes iota ids output and
// re-zeroes g_count for the next execution.
__global__ void gather_kernel(const float4* __restrict__ msgs4,
                              float* __restrict__ out,
                              float* __restrict__ ids_out,
                              int N, int has_ids) {
    int gw   = (blockIdx.x * blockDim.x + threadIdx.x) >> 5;
    int lane = threadIdx.x & 31;
    if (gw >= N) return;

    int cnt   = g_count[gw];
    int start = g_start[gw];
    float4 acc = make_float4(0.f, 0.f, 0.f, 0.f);

    if (cnt > 0) {
        int idx  = g_perm[start];
        int idxn = (cnt > 1) ? g_perm[start + 1] : 0;
        float4 v = ldg_stream_v4f(&msgs4[(size_t)idx * 32 + lane]);
        for (int j = 1; j < cnt; j++) {
            int idxn2 = (j + 1 < cnt) ? g_perm[start + j + 1] : 0;
            float4 v2 = ldg_stream_v4f(&msgs4[(size_t)idxn * 32 + lane]);
            acc.x += v.x; acc.y += v.y; acc.z += v.z; acc.w += v.w;
            v = v2; idxn = idxn2;
        }
        acc.x += v.x; acc.y += v.y; acc.z += v.z; acc.w += v.w;
    }

    float inv = (cnt > 0) ? (1.0f / (float)cnt) : 0.0f;
    acc.x *= inv; acc.y *= inv; acc.z *= inv; acc.w *= inv;
    stg_stream_v4f(&((float4*)out)[(size_t)gw * 32 + lane], acc);

    if (lane == 0) g_count[gw] = 0;                      // zero for next execution
    if (lane == 1 && has_ids) ids_out[gw] = (float)gw;   // iota ids output
}

// ---------- fallback path (generic D / oversized shapes) ----------
__device__ __forceinline__ void red_add_v4(float* addr, float4 v) {
    asm volatile("red.global.add.v4.f32 [%0], {%1, %2, %3, %4};"
                 :: "l"(addr), "f"(v.x), "f"(v.y), "f"(v.z), "f"(v.w) : "memory");
}
__device__ __forceinline__ void red_add_f32(float* addr, float v) {
    asm volatile("red.global.add.f32 [%0], %1;"
                 :: "l"(addr), "f"(v) : "memory");
}

__global__ void fb_init_kernel(float* __restrict__ sums, float* __restrict__ ids_out,
                               int N, int D, int has_ids) {
    long long total = (long long)N * D;
    for (long long i = blockIdx.x * (long long)blockDim.x + threadIdx.x;
         i < total; i += (long long)gridDim.x * blockDim.x)
        sums[i] = 0.f;
    for (long long i = blockIdx.x * (long long)blockDim.x + threadIdx.x;
         i < N; i += (long long)gridDim.x * blockDim.x) {
        if (i < MAX_NODES) g_fcounts[i] = 0.f;
        if (has_ids) ids_out[i] = (float)i;
    }
}

__global__ void fb_scatter_kernel(const void* __restrict__ ids,
                                  const float* __restrict__ msgs,
                                  float* __restrict__ sums, int M, int D) {
    bool is64 = detect_is64_block((const unsigned int*)ids, M);
    int gwarp = (blockIdx.x * blockDim.x + threadIdx.x) >> 5;
    int lane  = threadIdx.x & 31;
    if (gwarp >= M) return;
    int id = load_id(ids, gwarp, is64);
    const float* row = msgs + (size_t)gwarp * D;
    float* dst = sums + (size_t)id * D;
    for (int c = lane * 4; c + 3 < D; c += 128)
        red_add_v4(dst + c, *(const float4*)(row + c));
    for (int c = (D / 4) * 4 + lane; c < D; c += 32)
        red_add_f32(dst + c, row[c]);
    if (lane == 0) red_add_f32(&g_fcounts[id], 1.0f);
}

__global__ void fb_normalize_kernel(float* __restrict__ sums, int N, int D) {
    long long total = (long long)N * D;
    for (long long i = blockIdx.x * (long long)blockDim.x + threadIdx.x;
         i < total; i += (long long)gridDim.x * blockDim.x) {
        int row = (int)(i / D);
        float inv = 1.0f / fmaxf(g_fcounts[row], 1.0f);
        sums[i] *= inv;
    }
}

extern "C" void kernel_launch(void* const* d_in, const int* in_sizes, int n_in,
                              void* d_out, int out_size) {
    const void*  ids  = d_in[0];
    const float* msgs = (const float*)d_in[1];

    int M = in_sizes[0];
    int D = in_sizes[1] / M;   // 128

    int N, has_ids;
    if (out_size % (D + 1) == 0) { N = out_size / (D + 1); has_ids = 1; }
    else                          { N = out_size / D;       has_ids = 0; }

    float* out     = (float*)d_out;
    float* ids_out = out;
    float* sums    = has_ids ? (out + N) : out;

    int nb = (N + SCAN_TILE - 1) / SCAN_TILE;
    bool fast = (D == 128) && (N <= MAX_NODES) && (M <= PERM_CAP) && (nb <= SCAN_THREADS);

    if (fast) {
        {
            int blocks = (M / 4 + 255) / 256; if (blocks > 2048) blocks = 2048;
            if (blocks < 1) blocks = 1;
            rank_kernel<<<blocks, 256>>>(ids, M);
        }
        scan_partial<<<nb, SCAN_THREADS>>>(N);
        scan_final<<<nb, SCAN_THREADS>>>(N, nb);
        {
            int blocks = (M / 4 + 255) / 256; if (blocks > 2048) blocks = 2048;
            if (blocks < 1) blocks = 1;
            place_kernel<<<blocks, 256>>>(ids, M);
        }
        {
            long long threads = (long long)N * 32;
            int blocks = (int)((threads + 255) / 256);
            gather_kernel<<<blocks, 256>>>((const float4*)msgs, sums, ids_out, N, has_ids);
        }
    } else {
        {
            long long total = (long long)N * D;
            int blocks = (int)((total + 255) / 256); if (blocks > 4096) blocks = 4096;
            fb_init_kernel<<<blocks, 256>>>(sums, ids_out, N, D, has_ids);
        }
        {
            long long threads = (long long)M * 32;
            int blocks = (int)((threads + 255) / 256);
            fb_scatter_kernel<<<blocks, 256>>>(ids, msgs, sums, M, D);
        }
        {
            long long total = (long long)N * D;
            int blocks = (int)((total + 255) / 256); if (blocks > 4096) blocks = 4096;
            fb_normalize_kernel<<<blocks, 256>>>(sums, N, D);
        }
    }
}

// round 15
// speedup vs baseline: 1.0739x; 1.0739x over previous
#include <cuda_runtime.h>
#include <cuda_bf16.h>
#include <stdint.h>

// Scatter-mean via counting-sort + gather (no atomics in the hot loop).
// Pipeline (5 launches): rank (inline dtype detect + hist + rank-within-node,
// only atomic pass) -> scan_partial -> scan_final (inline tops) -> place
// (atomic-free, 4-wide) -> gather (2-deep pipeline, L1-bypass streaming row
// loads). Read-once LOADS use L1::no_allocate; all STORES stay default-cached
// (no_allocate on scattered stores measured as a regression -- L1 write
// combining matters there).
// Fallback to a direct-atomic path for shapes exceeding static scratch.

#define MAX_NODES (1 << 20)
#define PERM_CAP  (1 << 21)
#define SCAN_TILE 1024
#define SCAN_THREADS 512
#define MAX_SCAN_BLOCKS ((MAX_NODES + SCAN_TILE - 1) / SCAN_TILE)

__device__ int g_count[MAX_NODES];       // zero at entry of every execution
__device__ int g_start[MAX_NODES];
__device__ int g_rank[PERM_CAP];
__device__ int g_perm[PERM_CAP];
__device__ int g_bsum[MAX_SCAN_BLOCKS];
__device__ float g_fcounts[MAX_NODES];   // fallback path only

// ---- streaming (no L1 allocation) load helpers ----
__device__ __forceinline__ float4 ldg_stream_v4f(const float4* p) {
    float4 v;
    asm volatile("ld.global.nc.L1::no_allocate.v4.f32 {%0, %1, %2, %3}, [%4];"
                 : "=f"(v.x), "=f"(v.y), "=f"(v.z), "=f"(v.w) : "l"(p));
    return v;
}
__device__ __forceinline__ int4 ldg_stream_v4i(const int4* p) {
    int4 v;
    asm volatile("ld.global.nc.L1::no_allocate.v4.s32 {%0, %1, %2, %3}, [%4];"
                 : "=r"(v.x), "=r"(v.y), "=r"(v.z), "=r"(v.w) : "l"(p));
    return v;
}
__device__ __forceinline__ longlong2 ldg_stream_v2l(const longlong2* p) {
    longlong2 v;
    asm volatile("ld.global.nc.L1::no_allocate.v2.s64 {%0, %1}, [%2];"
                 : "=l"(v.x), "=l"(v.y) : "l"(p));
    return v;
}

// Per-block inline dtype detection: examine 256 odd-position 32-bit words from
// this block's own region. int64 ids < 2^32 have all-zero high words; int32
// random ids make some odd word nonzero with overwhelming probability. The
// degenerate all-zero case decodes identically either way.
__device__ __forceinline__ bool detect_is64_block(const unsigned int* words, int M) {
    int t = threadIdx.x & 255;
    int span = M >> 1;                 // number of (even,odd) pairs within M words
    unsigned int w = 0u;
    if (span > 0) {
        int wbase = (int)blockIdx.x * 256;
        if (span > 256) wbase %= (span - 255); else wbase = 0;
        int p = wbase + t;
        if (p < span) w = words[2 * p + 1];
    }
    return __syncthreads_or((int)w) == 0;   // all high words zero -> int64
}

__device__ __forceinline__ int load_id(const void* ids, int i, bool is64) {
    return is64 ? (int)((const long long*)ids)[i] : ((const int*)ids)[i];
}

// Histogram + rank-within-node: the only returning-atomic pass.
// 4 independent atomic chains in flight per thread-iteration.
__global__ void rank_kernel(const void* __restrict__ ids, int M) {
    bool is64 = detect_is64_block((const unsigned int*)ids, M);
    int t = blockIdx.x * blockDim.x + threadIdx.x;
    int stride = gridDim.x * blockDim.x;
    int M4 = M >> 2;
    if (is64) {
        const longlong2* p = (const longlong2*)ids;
        for (int i = t; i < M4; i += stride) {
            longlong2 a = ldg_stream_v2l(&p[2 * i]);
            longlong2 b = ldg_stream_v2l(&p[2 * i + 1]);
            int r0 = atomicAdd(&g_count[(int)a.x], 1);
            int r1 = atomicAdd(&g_count[(int)a.y], 1);
            int r2 = atomicAdd(&g_count[(int)b.x], 1);
            int r3 = atomicAdd(&g_count[(int)b.y], 1);
            ((int4*)g_rank)[i] = make_int4(r0, r1, r2, r3);
        }
    } else {
        const int4* p = (const int4*)ids;
        for (int i = t; i < M4; i += stride) {
            int4 a = ldg_stream_v4i(&p[i]);
            int r0 = atomicAdd(&g_count[a.x], 1);
            int r1 = atomicAdd(&g_count[a.y], 1);
            int r2 = atomicAdd(&g_count[a.z], 1);
            int r3 = atomicAdd(&g_count[a.w], 1);
            ((int4*)g_rank)[i] = make_int4(r0, r1, r2, r3);
        }
    }
    for (int i = M4 * 4 + t; i < M; i += stride)
        g_rank[i] = atomicAdd(&g_count[load_id(ids, i, is64)], 1);
}

// ----- 2-stage scan: partial sums -> final rescan with inline tops scan -----
__global__ void scan_partial(int N) {
    __shared__ int wsum[SCAN_THREADS / 32];
    int b = blockIdx.x, tid = threadIdx.x;
    int lane = tid & 31, warp = tid >> 5;
    int base = b * SCAN_TILE + tid * 2;
    int s = 0;
    #pragma unroll
    for (int k = 0; k < 2; k++) {
        int i = base + k;
        if (i < N) s += g_count[i];
    }
    #pragma unroll
    for (int o = 16; o > 0; o >>= 1) s += __shfl_down_sync(0xffffffffu, s, o);
    if (lane == 0) wsum[warp] = s;
    __syncthreads();
    if (warp == 0) {
        int w = (lane < SCAN_THREADS / 32) ? wsum[lane] : 0;
        #pragma unroll
        for (int o = 16; o > 0; o >>= 1) w += __shfl_down_sync(0xffffffffu, w, o);
        if (lane == 0) g_bsum[b] = w;
    }
}

__global__ void scan_final(int N, int nb) {
    __shared__ int wsum[32];
    __shared__ int sboff[1024];
    int b = blockIdx.x, tid = threadIdx.x;
    int lane = tid & 31, warp = tid >> 5;

    // Inline exclusive scan of the nb block sums (nb <= SCAN_THREADS).
    {
        int s = (tid < nb) ? g_bsum[tid] : 0;
        int x = s;
        #pragma unroll
        for (int o = 1; o < 32; o <<= 1) {
            int y = __shfl_up_sync(0xffffffffu, x, o);
            if (lane >= o) x += y;
        }
        if (lane == 31) wsum[warp] = x;
        __syncthreads();
        if (warp == 0) {
            int w = (lane < SCAN_THREADS / 32) ? wsum[lane] : 0;
            #pragma unroll
            for (int o = 1; o < 32; o <<= 1) {
                int y = __shfl_up_sync(0xffffffffu, w, o);
                if (lane >= o) w += y;
            }
            wsum[lane] = w;
        }
        __syncthreads();
        if (tid < nb) sboff[tid] = x - s + (warp > 0 ? wsum[warp - 1] : 0);
        __syncthreads();
    }
    int boff = sboff[b];
    __syncthreads();   // wsum reuse below

    int base = b * SCAN_TILE + tid * 2;
    int v[2]; int s = 0;
    #pragma unroll
    for (int k = 0; k < 2; k++) {
        int i = base + k;
        v[k] = (i < N) ? g_count[i] : 0;
        s += v[k];
    }
    int x = s;
    #pragma unroll
    for (int o = 1; o < 32; o <<= 1) {
        int y = __shfl_up_sync(0xffffffffu, x, o);
        if (lane >= o) x += y;
    }
    if (lane == 31) wsum[warp] = x;
    __syncthreads();
    if (warp == 0) {
        int w = (lane < SCAN_THREADS / 32) ? wsum[lane] : 0;
        #pragma unroll
        for (int o = 1; o < 32; o <<= 1) {
            int y = __shfl_up_sync(0xffffffffu, w, o);
            if (lane >= o) w += y;
        }
        wsum[lane] = w;
    }
    __syncthreads();
    int run = x - s + (warp > 0 ? wsum[warp - 1] : 0) + boff;
    #pragma unroll
    for (int k = 0; k < 2; k++) {
        int i = base + k;
        if (i < N) {
            g_start[i] = run;
            run += v[k];
        }
    }
}

// Atomic-free permutation: perm[start[id] + rank[i]] = i. 4-wide.
// Sequential id/rank loads bypass L1; g_start gather and perm stores stay
// default-cached (store write-combining + L1-resident g_start).
__global__ void place_kernel(const void* __restrict__ ids, int M) {
    bool is64 = detect_is64_block((const unsigned int*)ids, M);
    int t = blockIdx.x * blockDim.x + threadIdx.x;
    int stride = gridDim.x * blockDim.x;
    int M4 = M >> 2;
    if (is64) {
        const longlong2* p = (const longlong2*)ids;
        for (int i = t; i < M4; i += stride) {
            longlong2 a = ldg_stream_v2l(&p[2 * i]);
            longlong2 b = ldg_stream_v2l(&p[2 * i + 1]);
            int4 r = ldg_stream_v4i(&((const int4*)g_rank)[i]);
            int base = 4 * i;
            g_perm[g_start[(int)a.x] + r.x] = base;
            g_perm[g_start[(int)a.y] + r.y] = base + 1;
            g_perm[g_start[(int)b.x] + r.z] = base + 2;
            g_perm[g_start[(int)b.y] + r.w] = base + 3;
        }
    } else {
        const int4* p = (const int4*)ids;
        for (int i = t; i < M4; i += stride) {
            int4 a = ldg_stream_v4i(&p[i]);
            int4 r = ldg_stream_v4i(&((const int4*)g_rank)[i]);
            int base = 4 * i;
            g_perm[g_start[a.x] + r.x] = base;
            g_perm[g_start[a.y] + r.y] = base + 1;
            g_perm[g_start[a.z] + r.z] = base + 2;
            g_perm[g_start[a.w] + r.w] = base + 3;
        }
    }
    for (int i = M4 * 4 + t; i < M; i += stride) {
        int id = load_id(ids, i, is64);
        g_perm[g_start[id] + g_rank[i]] = i;
    }
}

// One warp per node; D == 128 (32 float4 per row, 1 per lane), 2-deep pipeline.
// Row loads bypass L1 (read-once streaming); stores default. Also writes iota
// ids output and re-zeroes g_count for the next execution.
__global__ void gather_kernel(const float4* __restrict__ msgs4,
                              float* __restrict__ out,
                              float* __restrict__ ids_out,
                              int N, int has_ids) {
    int gw   = (blockIdx.x * blockDim.x + threadIdx.x) >> 5;
    int lane = threadIdx.x & 31;
    if (gw >= N) return;

    int cnt   = g_count[gw];
    int start = g_start[gw];
    float4 acc = make_float4(0.f, 0.f, 0.f, 0.f);

    if (cnt > 0) {
        int idx  = g_perm[start];
        int idxn = (cnt > 1) ? g_perm[start + 1] : 0;
        float4 v = ldg_stream_v4f(&msgs4[(size_t)idx * 32 + lane]);
        for (int j = 1; j < cnt; j++) {
            int idxn2 = (j + 1 < cnt) ? g_perm[start + j + 1] : 0;
            float4 v2 = ldg_stream_v4f(&msgs4[(size_t)idxn * 32 + lane]);
            acc.x += v.x; acc.y += v.y; acc.z += v.z; acc.w += v.w;
            v = v2; idxn = idxn2;
        }
        acc.x += v.x; acc.y += v.y; acc.z += v.z; acc.w += v.w;
    }

    float inv = (cnt > 0) ? (1.0f / (float)cnt) : 0.0f;
    acc.x *= inv; acc.y *= inv; acc.z *= inv; acc.w *= inv;
    ((float4*)out)[(size_t)gw * 32 + lane] = acc;

    if (lane == 0) g_count[gw] = 0;                      // zero for next execution
    if (lane == 1 && has_ids) ids_out[gw] = (float)gw;   // iota ids output
}

// ---------- fallback path (generic D / oversized shapes) ----------
__device__ __forceinline__ void red_add_v4(float* addr, float4 v) {
    asm volatile("red.global.add.v4.f32 [%0], {%1, %2, %3, %4};"
                 :: "l"(addr), "f"(v.x), "f"(v.y), "f"(v.z), "f"(v.w) : "memory");
}
__device__ __forceinline__ void red_add_f32(float* addr, float v) {
    asm volatile("red.global.add.f32 [%0], %1;"
                 :: "l"(addr), "f"(v) : "memory");
}

__global__ void fb_init_kernel(float* __restrict__ sums, float* __restrict__ ids_out,
                               int N, int D, int has_ids) {
    long long total = (long long)N * D;
    for (long long i = blockIdx.x * (long long)blockDim.x + threadIdx.x;
         i < total; i += (long long)gridDim.x * blockDim.x)
        sums[i] = 0.f;
    for (long long i = blockIdx.x * (long long)blockDim.x + threadIdx.x;
         i < N; i += (long long)gridDim.x * blockDim.x) {
        if (i < MAX_NODES) g_fcounts[i] = 0.f;
        if (has_ids) ids_out[i] = (float)i;
    }
}

__global__ void fb_scatter_kernel(const void* __restrict__ ids,
                                  const float* __restrict__ msgs,
                                  float* __restrict__ sums, int M, int D) {
    bool is64 = detect_is64_block((const unsigned int*)ids, M);
    int gwarp = (blockIdx.x * blockDim.x + threadIdx.x) >> 5;
    int lane  = threadIdx.x & 31;
    if (gwarp >= M) return;
    int id = load_id(ids, gwarp, is64);
    const float* row = msgs + (size_t)gwarp * D;
    float* dst = sums + (size_t)id * D;
    for (int c = lane * 4; c + 3 < D; c += 128)
        red_add_v4(dst + c, *(const float4*)(row + c));
    for (int c = (D / 4) * 4 + lane; c < D; c += 32)
        red_add_f32(dst + c, row[c]);
    if (lane == 0) red_add_f32(&g_fcounts[id], 1.0f);
}

__global__ void fb_normalize_kernel(float* __restrict__ sums, int N, int D) {
    long long total = (long long)N * D;
    for (long long i = blockIdx.x * (long long)blockDim.x + threadIdx.x;
         i < total; i += (long long)gridDim.x * blockDim.x) {
        int row = (int)(i / D);
        float inv = 1.0f / fmaxf(g_fcounts[row], 1.0f);
        sums[i] *= inv;
    }
}

extern "C" void kernel_launch(void* const* d_in, const int* in_sizes, int n_in,
                              void* d_out, int out_size) {
    const void*  ids  = d_in[0];
    const float* msgs = (const float*)d_in[1];

    int M = in_sizes[0];
    int D = in_sizes[1] / M;   // 128

    int N, has_ids;
    if (out_size % (D + 1) == 0) { N = out_size / (D + 1); has_ids = 1; }
    else                          { N = out_size / D;       has_ids = 0; }

    float* out     = (float*)d_out;
    float* ids_out = out;
    float* sums    = has_ids ? (out + N) : out;

    int nb = (N + SCAN_TILE - 1) / SCAN_TILE;
    bool fast = (D == 128) && (N <= MAX_NODES) && (M <= PERM_CAP) && (nb <= SCAN_THREADS);

    if (fast) {
        {
            int blocks = (M / 4 + 255) / 256; if (blocks > 2048) blocks = 2048;
            if (blocks < 1) blocks = 1;
            rank_kernel<<<blocks, 256>>>(ids, M);
        }
        scan_partial<<<nb, SCAN_THREADS>>>(N);
        scan_final<<<nb, SCAN_THREADS>>>(N, nb);
        {
            int blocks = (M / 4 + 255) / 256; if (blocks > 2048) blocks = 2048;
            if (blocks < 1) blocks = 1;
            place_kernel<<<blocks, 256>>>(ids, M);
        }
        {
            long long threads = (long long)N * 32;
            int blocks = (int)((threads + 255) / 256);
            gather_kernel<<<blocks, 256>>>((const float4*)msgs, sums, ids_out, N, has_ids);
        }
    } else {
        {
            long long total = (long long)N * D;
            int blocks = (int)((total + 255) / 256); if (blocks > 4096) blocks = 4096;
            fb_init_kernel<<<blocks, 256>>>(sums, ids_out, N, D, has_ids);
        }
        {
            long long threads = (long long)M * 32;
            int blocks = (int)((threads + 255) / 256);
            fb_scatter_kernel<<<blocks, 256>>>(ids, msgs, sums, M, D);
        }
        {
            long long total = (long long)N * D;
            int blocks = (int)((total + 255) / 256); if (blocks > 4096) blocks = 4096;
            fb_normalize_kernel<<<blocks, 256>>>(sums, N, D);
        }
    }
}